// round 7
// baseline (speedup 1.0000x reference)
#include <cuda_runtime.h>
#include <cuda_bf16.h>
#include <cuda_fp16.h>
#include <mma.h>
#include <cstdint>

using namespace nvcuda;

#define B_  512
#define T_  256
#define V_  1000
#define E_  256
#define H_  512
#define G_  2048   // 4*H

#define LDW 520    // padded bf16 smem pitch (1040B) — conflict-free
#define LDG_ 132   // padded float pitch for gate buffer

// ---------------- fast activations / helpers ----------------
__device__ __forceinline__ float tanh_fast(float x) {
    float y; asm("tanh.approx.f32 %0, %1;" : "=f"(y) : "f"(x)); return y;
}
__device__ __forceinline__ float sigmoid_fast(float x) {
    return fmaf(0.5f, tanh_fast(0.5f * x), 0.5f);
}
__device__ __forceinline__ uint32_t smem_u32(const void* p) {
    uint32_t a;
    asm("{ .reg .u64 t; cvta.to.shared.u64 t, %1; cvt.u32.u64 %0, t; }" : "=r"(a) : "l"(p));
    return a;
}
#define LDMATRIX_X4(r0, r1, r2, r3, addr) \
    asm volatile("ldmatrix.sync.aligned.m8n8.x4.shared.b16 {%0,%1,%2,%3}, [%4];" \
        : "=r"(r0), "=r"(r1), "=r"(r2), "=r"(r3) : "r"(addr))
#define MMA_16816(d, a0, a1, a2, a3, b0, b1) \
    asm volatile("mma.sync.aligned.m16n8k16.row.col.f32.bf16.bf16.f32 " \
        "{%0,%1,%2,%3}, {%4,%5,%6,%7}, {%8,%9}, {%0,%1,%2,%3};" \
        : "+f"(d[0]), "+f"(d[1]), "+f"(d[2]), "+f"(d[3]) \
        : "r"(a0), "r"(a1), "r"(a2), "r"(a3), "r"(b0), "r"(b1))

// ---------------- static device scratch ----------------
__device__ __align__(16) __nv_bfloat16 g_H[(T_ + 1)][B_][H_];   // h states (~134MB)
__device__ __align__(16) float          g_tab[V_][G_];          // interleaved [v][4*h+q] (8MB)
__device__ __align__(16) __nv_bfloat16  g_Whh[G_][H_];          // bf16 W_hh1 (2MB)
__device__ __align__(16) __nv_bfloat16  g_Wout[1024][H_];       // bf16 W_out padded (1MB)
__device__ __align__(16) short          g_chars[T_][B_];
__device__ int g_cnt[8 * 32];
__device__ volatile int g_rel[8 * 32];

// ---------------- init ----------------
__global__ void init_kernel(const float* __restrict__ Whh1, const float* __restrict__ WoutF,
                            const void* __restrict__ gt_raw) {
    int stride = gridDim.x * blockDim.x;
    int tid0 = blockIdx.x * blockDim.x + threadIdx.x;
    if (tid0 < 8) { g_cnt[tid0 * 32] = 0; g_rel[tid0 * 32] = 0; }
    const int* p = (const int*)gt_raw;
    int z = (p[1] == 0) + (p[3] == 0) + (p[5] == 0) + (p[7] == 0) +
            (p[9] == 0) + (p[11] == 0) + (p[13] == 0) + (p[15] == 0);
    int is64 = (z == 8);
    for (int i = tid0; i < G_ * H_; i += stride) {
        ((__nv_bfloat16*)g_Whh)[i] = __float2bfloat16(Whh1[i]);
        if (i < 1024 * H_) {
            float v = (i < V_ * H_) ? WoutF[i] : 0.f;
            ((__nv_bfloat16*)g_Wout)[i] = __float2bfloat16(v);
        }
        if (i < B_ * H_) ((__nv_bfloat16*)g_H)[i] = __float2bfloat16(0.f);
        if (i < T_ * B_) {
            int t = i / B_, b = i % B_;
            int ch = 0;
            if (t > 0) {
                int idx = b * T_ + (t - 1);
                ch = is64 ? (int)((const long long*)gt_raw)[idx] : ((const int*)gt_raw)[idx];
            }
            ((short*)g_chars)[i] = (short)ch;
        }
    }
}

// ---------------- ih gate table (interleaved [v][4*h+q]) ----------------
__global__ void table_kernel(const float* __restrict__ emb, const float* __restrict__ Wih,
                             const float* __restrict__ bih, const float* __restrict__ bhh) {
    int gtile = blockIdx.x;
    int vtile = blockIdx.y;
    __shared__ float sE[64][65];
    __shared__ float sW[64][65];
    float acc[4][4] = {};
    int tm = threadIdx.x >> 4, tn = threadIdx.x & 15;
    for (int kc = 0; kc < 4; kc++) {
        for (int i = threadIdx.x; i < 64 * 64; i += 256) {
            int r = i >> 6, c = i & 63;
            int v = vtile * 64 + r;
            sE[r][c] = (v < V_) ? emb[v * E_ + kc * 64 + c] : 0.f;
            sW[r][c] = Wih[(gtile * 64 + r) * E_ + kc * 64 + c];
        }
        __syncthreads();
        #pragma unroll 8
        for (int k = 0; k < 64; k++) {
            float e[4], w[4];
            #pragma unroll
            for (int mi = 0; mi < 4; mi++) e[mi] = sE[tm * 4 + mi][k];
            #pragma unroll
            for (int ni = 0; ni < 4; ni++) w[ni] = sW[tn * 4 + ni][k];
            #pragma unroll
            for (int mi = 0; mi < 4; mi++)
                #pragma unroll
                for (int ni = 0; ni < 4; ni++) acc[mi][ni] += e[mi] * w[ni];
        }
        __syncthreads();
    }
    #pragma unroll
    for (int mi = 0; mi < 4; mi++) {
        int v = vtile * 64 + tm * 4 + mi;
        if (v >= V_) continue;
        #pragma unroll
        for (int ni = 0; ni < 4; ni++) {
            int g = gtile * 64 + tn * 4 + ni;            // gate-major index q*512+h
            g_tab[v][(g & 511) * 4 + (g >> 9)] = acc[mi][ni] + bih[g] + bhh[g];
        }
    }
}

// ---------------- persistent recurrence (round-4 wmma structure + tab prefetch) ----------------
// 128 blocks: bt = bid>>4 (8 x 64 batch), gt = bid&15 (16 x 32 h-cols -> 128 gate cols).
#define SMEM_RECUR ((128 * LDW + 64 * LDW) * 2)

__global__ __launch_bounds__(256, 1) void recur_kernel() {
    extern __shared__ __nv_bfloat16 smem[];
    __nv_bfloat16* sW = smem;               // 128 x LDW
    __nv_bfloat16* sA = smem + 128 * LDW;   // 64 x LDW
    float* sG = (float*)sA;                 // 64 x LDG_ (reuse after GEMM)

    const int gt = blockIdx.x & 15;
    const int bt = blockIdx.x >> 4;
    const int b0 = bt * 64;
    const int tid = threadIdx.x;

    // stage W slice once: row r: gate q=r>>5, h-col gt*32+(r&31)
    for (int i = tid; i < 128 * 64; i += 256) {
        int r = i >> 6, c = i & 63;
        int grow = (r >> 5) * H_ + gt * 32 + (r & 31);
        ((uint4*)(sW + r * LDW))[c] = *(const uint4*)&g_Whh[grow][c * 8];
    }
    __syncthreads();

    const int warp = tid >> 5, lane = tid & 31;
    const int wm = warp >> 2;   // 0..1 (32 batch rows)
    const int wn = warp & 3;    // 0..3 (32 gate cols)
    const int hcol = gt * 32 + lane;   // pointwise h column for this thread

    float creg[8];
    #pragma unroll
    for (int j = 0; j < 8; j++) creg[j] = 0.f;

    for (int t = 0; t < T_; t++) {
        // prefetch gate-table float4s (depend only on t) — hidden under staging+GEMM
        float4 tb4[8];
        #pragma unroll
        for (int k = 0; k < 8; k++) {
            int ch = g_chars[t][b0 + warp + 8 * k];
            tb4[k] = ((const float4*)g_tab[ch])[hcol];
        }

        // stage A = h_t tile [64 x 512]
        for (int i = tid; i < 64 * 64; i += 256) {
            int r = i >> 6, c = i & 63;
            ((uint4*)(sA + r * LDW))[c] = ((const uint4*)&g_H[t][b0 + r][0])[c];
        }
        __syncthreads();

        wmma::fragment<wmma::accumulator, 16, 16, 16, float> acc[2][2];
        #pragma unroll
        for (int mi = 0; mi < 2; mi++)
            #pragma unroll
            for (int ni = 0; ni < 2; ni++) wmma::fill_fragment(acc[mi][ni], 0.f);

        #pragma unroll 4
        for (int kk = 0; kk < 32; kk++) {
            wmma::fragment<wmma::matrix_b, 16, 16, 16, __nv_bfloat16, wmma::col_major> fb[2];
            #pragma unroll
            for (int ni = 0; ni < 2; ni++)
                wmma::load_matrix_sync(fb[ni], sW + (wn * 32 + ni * 16) * LDW + kk * 16, LDW);
            #pragma unroll
            for (int mi = 0; mi < 2; mi++) {
                wmma::fragment<wmma::matrix_a, 16, 16, 16, __nv_bfloat16, wmma::row_major> fa;
                wmma::load_matrix_sync(fa, sA + (wm * 32 + mi * 16) * LDW + kk * 16, LDW);
                #pragma unroll
                for (int ni = 0; ni < 2; ni++)
                    wmma::mma_sync(acc[mi][ni], fa, fb[ni], acc[mi][ni]);
            }
        }
        __syncthreads();

        #pragma unroll
        for (int mi = 0; mi < 2; mi++)
            #pragma unroll
            for (int ni = 0; ni < 2; ni++)
                wmma::store_matrix_sync(sG + (wm * 32 + mi * 16) * LDG_ + (wn * 32 + ni * 16),
                                        acc[mi][ni], LDG_, wmma::mem_row_major);
        __syncthreads();

        // fused LSTM pointwise; tab values already in registers
        #pragma unroll
        for (int k = 0; k < 8; k++) {
            int bl = warp + 8 * k;          // (tid + k*256)>>5
            float gi = sG[bl * LDG_ + lane]      + tb4[k].x;
            float gf = sG[bl * LDG_ + 32 + lane] + tb4[k].y;
            float gg = sG[bl * LDG_ + 64 + lane] + tb4[k].z;
            float go = sG[bl * LDG_ + 96 + lane] + tb4[k].w;
            gi = sigmoid_fast(gi);
            gf = sigmoid_fast(gf);
            gg = tanh_fast(gg);
            go = sigmoid_fast(go);
            float c = fmaf(gf, creg[k], gi * gg);
            creg[k] = c;
            g_H[t + 1][b0 + bl][hcol] = __float2bfloat16(go * tanh_fast(c));
        }

        // per-bt barrier across the 16 gt blocks
        __threadfence();
        __syncthreads();
        if (tid == 0) {
            int v = atomicAdd(&g_cnt[bt * 32], 1);
            if (v == 15) {
                g_cnt[bt * 32] = 0;
                __threadfence();
                atomicExch((int*)&g_rel[bt * 32], t + 1);
            } else {
                while (g_rel[bt * 32] < t + 1) __nanosleep(32);
                __threadfence();
            }
        }
        __syncthreads();
    }
}

// ---------------- fused projection + log_softmax -> d_out ----------------
// 2048 blocks, 256 thr. Block = 64 rows x full 1024 cols.
// SMEM: sV 64x1032 fp16 values | sA 64x72 bf16 | sB 256x72 bf16 | sBias 1024 f32.
#define SV_PITCH 1032
#define FUSE_SMEM (64 * SV_PITCH * 2 + (64 * 72 + 256 * 72) * 2 + 1024 * 4)

__global__ __launch_bounds__(256, 1) void out_kernel(float* __restrict__ out,
                                                     const float* __restrict__ bout) {
    extern __shared__ char fsm[];
    __half* sV = (__half*)fsm;
    __nv_bfloat16* sA = (__nv_bfloat16*)(fsm + 64 * SV_PITCH * 2);
    __nv_bfloat16* sB = sA + 64 * 72;
    float* sBias = (float*)(fsm + 64 * SV_PITCH * 2 + (64 * 72 + 256 * 72) * 2);

    const int mt = blockIdx.x;
    const __nv_bfloat16* A = &g_H[1][0][0];   // [131072][512]
    const int tid = threadIdx.x, warp = tid >> 5, lane = tid & 31;
    const int wm = warp >> 2, wn = warp & 3;
    const int g8 = lane >> 2, t4 = lane & 3;

    for (int i = tid; i < 1024; i += 256) sBias[i] = (i < V_) ? bout[i] : 0.f;

    const uint32_t sA32 = smem_u32(sA), sB32 = smem_u32(sB);
    uint32_t aAddr[2], bAddr[4];
    #pragma unroll
    for (int mi = 0; mi < 2; mi++)
        aAddr[mi] = sA32 + (uint32_t)(((wm * 32 + mi * 16 + (lane & 15)) * 72 + (lane >> 4) * 8) * 2);
    #pragma unroll
    for (int nj = 0; nj < 4; nj++)
        bAddr[nj] = sB32 + (uint32_t)(((wn * 64 + nj * 16 + (lane & 15)) * 72 + (lane >> 4) * 8) * 2);

    for (int nt = 0; nt < 4; nt++) {
        float acc[2][8][4];
        #pragma unroll
        for (int mi = 0; mi < 2; mi++)
            #pragma unroll
            for (int n8 = 0; n8 < 8; n8++)
                #pragma unroll
                for (int e = 0; e < 4; e++) acc[mi][n8][e] = 0.f;

        for (int kc = 0; kc < 8; kc++) {
            #pragma unroll
            for (int i = tid; i < 512; i += 256) {
                int r = i >> 3, c8 = i & 7;
                *(uint4*)(sA + r * 72 + c8 * 8) =
                    *(const uint4*)&A[(mt * 64 + r) * 512 + kc * 64 + c8 * 8];
            }
            #pragma unroll
            for (int i = tid; i < 2048; i += 256) {
                int n = i >> 3, c8 = i & 7;
                *(uint4*)(sB + n * 72 + c8 * 8) =
                    *(const uint4*)&g_Wout[nt * 256 + n][kc * 64 + c8 * 8];
            }
            __syncthreads();
            #pragma unroll
            for (int kk = 0; kk < 4; kk++) {
                uint32_t a[2][4];
                #pragma unroll
                for (int mi = 0; mi < 2; mi++)
                    LDMATRIX_X4(a[mi][0], a[mi][1], a[mi][2], a[mi][3], aAddr[mi] + kk * 32);
                #pragma unroll
                for (int nj = 0; nj < 4; nj++) {
                    uint32_t bm[4];
                    LDMATRIX_X4(bm[0], bm[1], bm[2], bm[3], bAddr[nj] + kk * 32);
                    #pragma unroll
                    for (int mi = 0; mi < 2; mi++) {
                        MMA_16816(acc[mi][nj * 2 + 0], a[mi][0], a[mi][1], a[mi][2], a[mi][3],
                                  bm[0], bm[2]);
                        MMA_16816(acc[mi][nj * 2 + 1], a[mi][0], a[mi][1], a[mi][2], a[mi][3],
                                  bm[1], bm[3]);
                    }
                }
            }
            __syncthreads();
        }

        // epilogue: acc -> fp16 value buffer (known m16n8 layout; conflict-free)
        #pragma unroll
        for (int mi = 0; mi < 2; mi++) {
            int row = wm * 32 + mi * 16 + g8;
            #pragma unroll
            for (int n8 = 0; n8 < 8; n8++) {
                int col = nt * 256 + wn * 64 + n8 * 8 + 2 * t4;
                *(__half2*)&sV[row * SV_PITCH + col] =
                    __floats2half2_rn(acc[mi][n8][0], acc[mi][n8][1]);
                *(__half2*)&sV[(row + 8) * SV_PITCH + col] =
                    __floats2half2_rn(acc[mi][n8][2], acc[mi][n8][3]);
            }
        }
    }
    __syncthreads();

    // in-block log_softmax: warp w handles rows w*8..w*8+7
    #pragma unroll 1
    for (int rr = 0; rr < 8; rr++) {
        int row = warp * 8 + rr;
        float v[32];
        float mx = -1e30f;
        #pragma unroll
        for (int j = 0; j < 16; j++) {
            int col = 2 * (lane + j * 32);
            __half2 h2 = *(__half2*)&sV[row * SV_PITCH + col];
            float f0 = (col < V_) ? __half2float(__low2half(h2)) + sBias[col] : -1e30f;
            float f1 = (col + 1 < V_) ? __half2float(__high2half(h2)) + sBias[col + 1] : -1e30f;
            v[2 * j] = f0; v[2 * j + 1] = f1;
            mx = fmaxf(mx, fmaxf(f0, f1));
        }
        #pragma unroll
        for (int s = 16; s > 0; s >>= 1) mx = fmaxf(mx, __shfl_xor_sync(0xFFFFFFFF, mx, s));
        float sum = 0.f;
        #pragma unroll
        for (int j = 0; j < 32; j++) sum += __expf(v[j] - mx);
        #pragma unroll
        for (int s = 16; s > 0; s >>= 1) sum += __shfl_xor_sync(0xFFFFFFFF, sum, s);
        float lse = mx + logf(sum);

        int r = mt * 64 + row;
        int t = r >> 9, b = r & 511;
        float* o = out + ((size_t)b * T_ + t) * V_;
        #pragma unroll
        for (int j = 0; j < 16; j++) {
            int col = 2 * (lane + j * 32);
            if (col < V_) {
                float2 w2 = make_float2(v[2 * j] - lse, v[2 * j + 1] - lse);
                *(float2*)&o[col] = w2;
            }
        }
    }
}

// ---------------- launch ----------------
extern "C" void kernel_launch(void* const* d_in, const int* in_sizes, int n_in,
                              void* d_out, int out_size) {
    const void*  gt   = d_in[1];
    const float* emb  = (const float*)d_in[2];
    const float* Wih1 = (const float*)d_in[7];
    const float* Whh1 = (const float*)d_in[8];
    const float* bih1 = (const float*)d_in[9];
    const float* bhh1 = (const float*)d_in[10];
    const float* Wout = (const float*)d_in[11];
    const float* bout = (const float*)d_in[12];
    float* out = (float*)d_out;

    cudaFuncSetAttribute(recur_kernel, cudaFuncAttributeMaxDynamicSharedMemorySize, SMEM_RECUR);
    cudaFuncSetAttribute(out_kernel, cudaFuncAttributeMaxDynamicSharedMemorySize, FUSE_SMEM);

    init_kernel<<<1024, 256>>>(Whh1, Wout, gt);
    table_kernel<<<dim3(32, 16), 256>>>(emb, Wih1, bih1, bhh1);
    recur_kernel<<<128, 256, SMEM_RECUR>>>();
    out_kernel<<<2048, 256, FUSE_SMEM>>>(out, bout);
}

// round 8
// speedup vs baseline: 1.4744x; 1.4744x over previous
#include <cuda_runtime.h>
#include <cuda_bf16.h>
#include <mma.h>
#include <cstdint>

using namespace nvcuda;

#define B_  512
#define T_  256
#define V_  1000
#define E_  256
#define H_  512
#define G_  2048   // 4*H

#define LDW 520    // padded bf16 smem pitch (1040B) — conflict-free
#define LDG_ 132   // padded float pitch for gate buffer

// ---------------- fast activations / helpers ----------------
__device__ __forceinline__ float tanh_fast(float x) {
    float y; asm("tanh.approx.f32 %0, %1;" : "=f"(y) : "f"(x)); return y;
}
__device__ __forceinline__ float sigmoid_fast(float x) {
    return fmaf(0.5f, tanh_fast(0.5f * x), 0.5f);
}
__device__ __forceinline__ void st_release_gpu(int* p, int v) {
    asm volatile("st.release.gpu.global.b32 [%0], %1;" :: "l"(p), "r"(v) : "memory");
}
__device__ __forceinline__ int ld_acquire_gpu(const int* p) {
    int v;
    asm volatile("ld.acquire.gpu.global.b32 %0, [%1];" : "=r"(v) : "l"(p) : "memory");
    return v;
}

// ---------------- static device scratch ----------------
__device__ __align__(16) __nv_bfloat16 g_H[(T_ + 1)][B_][H_];   // h states (~134MB)
__device__ __align__(16) float          g_tab[V_][G_];          // interleaved [v][4*h+q] (8MB)
__device__ __align__(16) __nv_bfloat16  g_Whh[G_][H_];          // bf16 W_hh1 (2MB)
__device__ __align__(16) __nv_bfloat16  g_Wout[1024][H_];       // bf16 W_out padded (1MB)
__device__ __align__(16) float          g_logits[T_ * B_][1024];// fp32 logits scratch (~537MB)
__device__ __align__(16) short          g_chars[T_][B_];
__device__ int g_flags[128 * 32];        // per-(bt,gt) monotone step flags, 128B apart

// ---------------- init ----------------
__global__ void init_kernel(const float* __restrict__ Whh1, const float* __restrict__ WoutF,
                            const void* __restrict__ gt_raw) {
    int stride = gridDim.x * blockDim.x;
    int tid0 = blockIdx.x * blockDim.x + threadIdx.x;
    if (tid0 < 128) g_flags[tid0 * 32] = 0;
    const int* p = (const int*)gt_raw;
    int z = (p[1] == 0) + (p[3] == 0) + (p[5] == 0) + (p[7] == 0) +
            (p[9] == 0) + (p[11] == 0) + (p[13] == 0) + (p[15] == 0);
    int is64 = (z == 8);
    for (int i = tid0; i < G_ * H_; i += stride) {
        ((__nv_bfloat16*)g_Whh)[i] = __float2bfloat16(Whh1[i]);
        if (i < 1024 * H_) {
            float v = (i < V_ * H_) ? WoutF[i] : 0.f;
            ((__nv_bfloat16*)g_Wout)[i] = __float2bfloat16(v);
        }
        if (i < B_ * H_) ((__nv_bfloat16*)g_H)[i] = __float2bfloat16(0.f);
        if (i < T_ * B_) {
            int t = i / B_, b = i % B_;
            int ch = 0;
            if (t > 0) {
                int idx = b * T_ + (t - 1);
                ch = is64 ? (int)((const long long*)gt_raw)[idx] : ((const int*)gt_raw)[idx];
            }
            ((short*)g_chars)[i] = (short)ch;
        }
    }
}

// ---------------- ih gate table (interleaved [v][4*h+q]) ----------------
__global__ void table_kernel(const float* __restrict__ emb, const float* __restrict__ Wih,
                             const float* __restrict__ bih, const float* __restrict__ bhh) {
    int gtile = blockIdx.x;
    int vtile = blockIdx.y;
    __shared__ float sE[64][65];
    __shared__ float sW[64][65];
    float acc[4][4] = {};
    int tm = threadIdx.x >> 4, tn = threadIdx.x & 15;
    for (int kc = 0; kc < 4; kc++) {
        for (int i = threadIdx.x; i < 64 * 64; i += 256) {
            int r = i >> 6, c = i & 63;
            int v = vtile * 64 + r;
            sE[r][c] = (v < V_) ? emb[v * E_ + kc * 64 + c] : 0.f;
            sW[r][c] = Wih[(gtile * 64 + r) * E_ + kc * 64 + c];
        }
        __syncthreads();
        #pragma unroll 8
        for (int k = 0; k < 64; k++) {
            float e[4], w[4];
            #pragma unroll
            for (int mi = 0; mi < 4; mi++) e[mi] = sE[tm * 4 + mi][k];
            #pragma unroll
            for (int ni = 0; ni < 4; ni++) w[ni] = sW[tn * 4 + ni][k];
            #pragma unroll
            for (int mi = 0; mi < 4; mi++)
                #pragma unroll
                for (int ni = 0; ni < 4; ni++) acc[mi][ni] += e[mi] * w[ni];
        }
        __syncthreads();
    }
    #pragma unroll
    for (int mi = 0; mi < 4; mi++) {
        int v = vtile * 64 + tm * 4 + mi;
        if (v >= V_) continue;
        #pragma unroll
        for (int ni = 0; ni < 4; ni++) {
            int g = gtile * 64 + tn * 4 + ni;            // gate-major index q*512+h
            g_tab[v][(g & 511) * 4 + (g >> 9)] = acc[mi][ni] + bih[g] + bhh[g];
        }
    }
}

// ---------------- persistent recurrence (round-4 structure, new barrier, float4 tab) ----------------
// 128 blocks: bt = bid>>4 (8 x 64 batch), gt = bid&15 (16 x 32 h-cols -> 128 gate cols).
#define SMEM_RECUR ((128 * LDW + 64 * LDW) * 2)

__global__ __launch_bounds__(256, 1) void recur_kernel() {
    extern __shared__ __nv_bfloat16 smem[];
    __nv_bfloat16* sW = smem;               // 128 x LDW
    __nv_bfloat16* sA = smem + 128 * LDW;   // 64 x LDW
    float* sG = (float*)sA;                 // 64 x LDG_ (reuse after GEMM)

    const int gt = blockIdx.x & 15;
    const int bt = blockIdx.x >> 4;
    const int b0 = bt * 64;
    const int tid = threadIdx.x;

    // stage W slice once: row r: gate q=r>>5, h-col gt*32+(r&31)
    for (int i = tid; i < 128 * 64; i += 256) {
        int r = i >> 6, c = i & 63;
        int grow = (r >> 5) * H_ + gt * 32 + (r & 31);
        ((uint4*)(sW + r * LDW))[c] = *(const uint4*)&g_Whh[grow][c * 8];
    }
    __syncthreads();

    const int warp = tid >> 5, lane = tid & 31;
    const int wm = warp >> 2;   // 0..1 (32 batch rows)
    const int wn = warp & 3;    // 0..3 (32 gate cols)
    const int hcol = gt * 32 + lane;   // pointwise h column for this thread

    int* myflag = &g_flags[(bt * 16 + gt) * 32];
    int* peerflag = &g_flags[(bt * 16 + (tid & 15)) * 32];

    float creg[8];
    #pragma unroll
    for (int j = 0; j < 8; j++) creg[j] = 0.f;

    for (int t = 0; t < T_; t++) {
        // prefetch chars (depend only on t; 8 regs) — tab float4 loaded in pointwise
        short chs[8];
        #pragma unroll
        for (int k = 0; k < 8; k++) chs[k] = g_chars[t][b0 + warp + 8 * k];

        // stage A = h_t tile [64 x 512]
        for (int i = tid; i < 64 * 64; i += 256) {
            int r = i >> 6, c = i & 63;
            ((uint4*)(sA + r * LDW))[c] = ((const uint4*)&g_H[t][b0 + r][0])[c];
        }
        __syncthreads();

        wmma::fragment<wmma::accumulator, 16, 16, 16, float> acc[2][2];
        #pragma unroll
        for (int mi = 0; mi < 2; mi++)
            #pragma unroll
            for (int ni = 0; ni < 2; ni++) wmma::fill_fragment(acc[mi][ni], 0.f);

        #pragma unroll 4
        for (int kk = 0; kk < 32; kk++) {
            wmma::fragment<wmma::matrix_b, 16, 16, 16, __nv_bfloat16, wmma::col_major> fb[2];
            #pragma unroll
            for (int ni = 0; ni < 2; ni++)
                wmma::load_matrix_sync(fb[ni], sW + (wn * 32 + ni * 16) * LDW + kk * 16, LDW);
            #pragma unroll
            for (int mi = 0; mi < 2; mi++) {
                wmma::fragment<wmma::matrix_a, 16, 16, 16, __nv_bfloat16, wmma::row_major> fa;
                wmma::load_matrix_sync(fa, sA + (wm * 32 + mi * 16) * LDW + kk * 16, LDW);
                #pragma unroll
                for (int ni = 0; ni < 2; ni++)
                    wmma::mma_sync(acc[mi][ni], fa, fb[ni], acc[mi][ni]);
            }
        }
        __syncthreads();

        #pragma unroll
        for (int mi = 0; mi < 2; mi++)
            #pragma unroll
            for (int ni = 0; ni < 2; ni++)
                wmma::store_matrix_sync(sG + (wm * 32 + mi * 16) * LDG_ + (wn * 32 + ni * 16),
                                        acc[mi][ni], LDG_, wmma::mem_row_major);
        __syncthreads();

        // fused LSTM pointwise; one coalesced float4 tab load per element
        #pragma unroll
        for (int k = 0; k < 8; k++) {
            int bl = warp + 8 * k;          // (tid + k*256)>>5
            float4 tb = ((const float4*)g_tab[(int)chs[k]])[hcol];
            float gi = sG[bl * LDG_ + lane]      + tb.x;
            float gf = sG[bl * LDG_ + 32 + lane] + tb.y;
            float gg = sG[bl * LDG_ + 64 + lane] + tb.z;
            float go = sG[bl * LDG_ + 96 + lane] + tb.w;
            gi = sigmoid_fast(gi);
            gf = sigmoid_fast(gf);
            gg = tanh_fast(gg);
            go = sigmoid_fast(go);
            float c = fmaf(gf, creg[k], gi * gg);
            creg[k] = c;
            g_H[t + 1][b0 + bl][hcol] = __float2bfloat16(go * tanh_fast(c));
        }

        // release/acquire barrier across the 16 gt blocks of this bt
        __syncthreads();                       // all h stores happen-before tid0's release
        if (tid == 0) st_release_gpu(myflag, t + 1);
        if (tid < 16) {
            while (ld_acquire_gpu(peerflag) < t + 1) __nanosleep(32);
        }
        __syncthreads();                       // acquire edges propagate to whole CTA
    }
}

// ---------------- batched output projection (round-4, known-good) ----------------
__global__ __launch_bounds__(256, 2) void logits_kernel() {
    int nt = blockIdx.x, mt = blockIdx.y;
    __shared__ __nv_bfloat16 sA[64 * 72];
    __shared__ __nv_bfloat16 sB[256 * 72];
    const __nv_bfloat16* A = &g_H[1][0][0];  // [131072][512]

    int warp = threadIdx.x >> 5;
    int wm = warp >> 2;
    int wn = warp & 3;
    wmma::fragment<wmma::accumulator, 16, 16, 16, float> acc[2][4];
    #pragma unroll
    for (int mi = 0; mi < 2; mi++)
        #pragma unroll
        for (int ni = 0; ni < 4; ni++) wmma::fill_fragment(acc[mi][ni], 0.f);

    for (int kc = 0; kc < 8; kc++) {
        #pragma unroll
        for (int i = threadIdx.x; i < 512; i += 256) {
            int r = i >> 3, c8 = i & 7;
            *(uint4*)(sA + r * 72 + c8 * 8) = *(const uint4*)&A[(mt * 64 + r) * 512 + kc * 64 + c8 * 8];
        }
        #pragma unroll
        for (int i = threadIdx.x; i < 2048; i += 256) {
            int n = i >> 3, c8 = i & 7;
            *(uint4*)(sB + n * 72 + c8 * 8) = *(const uint4*)&g_Wout[nt * 256 + n][kc * 64 + c8 * 8];
        }
        __syncthreads();
        #pragma unroll
        for (int kk = 0; kk < 4; kk++) {
            wmma::fragment<wmma::matrix_a, 16, 16, 16, __nv_bfloat16, wmma::row_major> fa[2];
            #pragma unroll
            for (int mi = 0; mi < 2; mi++)
                wmma::load_matrix_sync(fa[mi], sA + (wm * 32 + mi * 16) * 72 + kk * 16, 72);
            #pragma unroll
            for (int ni = 0; ni < 4; ni++) {
                wmma::fragment<wmma::matrix_b, 16, 16, 16, __nv_bfloat16, wmma::col_major> fb;
                wmma::load_matrix_sync(fb, sB + (wn * 64 + ni * 16) * 72 + kk * 16, 72);
                #pragma unroll
                for (int mi = 0; mi < 2; mi++)
                    wmma::mma_sync(acc[mi][ni], fa[mi], fb, acc[mi][ni]);
            }
        }
        __syncthreads();
    }
    #pragma unroll
    for (int mi = 0; mi < 2; mi++)
        #pragma unroll
        for (int ni = 0; ni < 4; ni++) {
            int row = mt * 64 + wm * 32 + mi * 16;
            int col = nt * 256 + wn * 64 + ni * 16;
            wmma::store_matrix_sync(&g_logits[row][col], acc[mi][ni], 1024, wmma::mem_row_major);
        }
}

// ---------------- log_softmax + bias + remap (round-4, known-good) ----------------
__global__ __launch_bounds__(256, 4) void softmax_kernel(float* __restrict__ out,
                                                         const float* __restrict__ bout) {
    int row = blockIdx.x;
    int t = row >> 9, b = row & 511;
    const float* lg = g_logits[row];
    __shared__ float red[8];

    int lane = threadIdx.x & 31;
    int warp = threadIdx.x >> 5;

    float v[4];
    float mx = -1e30f;
    #pragma unroll
    for (int j = 0; j < 4; j++) {
        int c = threadIdx.x + j * 256;
        v[j] = (c < V_) ? (lg[c] + bout[c]) : -1e30f;
        mx = fmaxf(mx, v[j]);
    }
    #pragma unroll
    for (int s = 16; s > 0; s >>= 1) mx = fmaxf(mx, __shfl_xor_sync(0xFFFFFFFF, mx, s));
    if (lane == 0) red[warp] = mx;
    __syncthreads();
    float m0 = red[lane & 7];
    #pragma unroll
    for (int s = 4; s > 0; s >>= 1) m0 = fmaxf(m0, __shfl_xor_sync(0xFFFFFFFF, m0, s));
    mx = m0;

    float sum = 0.f;
    #pragma unroll
    for (int j = 0; j < 4; j++) {
        int c = threadIdx.x + j * 256;
        if (c < V_) sum += __expf(v[j] - mx);
    }
    #pragma unroll
    for (int s = 16; s > 0; s >>= 1) sum += __shfl_xor_sync(0xFFFFFFFF, sum, s);
    __syncthreads();
    if (lane == 0) red[warp] = sum;
    __syncthreads();
    float s0 = red[lane & 7];
    #pragma unroll
    for (int s = 4; s > 0; s >>= 1) s0 += __shfl_xor_sync(0xFFFFFFFF, s0, s);
    float lse = mx + logf(s0);

    float* o = out + ((size_t)b * T_ + t) * V_;
    #pragma unroll
    for (int j = 0; j < 4; j++) {
        int c = threadIdx.x + j * 256;
        if (c < V_) o[c] = v[j] - lse;
    }
}

// ---------------- launch ----------------
extern "C" void kernel_launch(void* const* d_in, const int* in_sizes, int n_in,
                              void* d_out, int out_size) {
    const void*  gt   = d_in[1];
    const float* emb  = (const float*)d_in[2];
    const float* Wih1 = (const float*)d_in[7];
    const float* Whh1 = (const float*)d_in[8];
    const float* bih1 = (const float*)d_in[9];
    const float* bhh1 = (const float*)d_in[10];
    const float* Wout = (const float*)d_in[11];
    const float* bout = (const float*)d_in[12];
    float* out = (float*)d_out;

    cudaFuncSetAttribute(recur_kernel, cudaFuncAttributeMaxDynamicSharedMemorySize, SMEM_RECUR);

    init_kernel<<<1024, 256>>>(Whh1, Wout, gt);
    table_kernel<<<dim3(32, 16), 256>>>(emb, Wih1, bih1, bhh1);
    recur_kernel<<<128, 256, SMEM_RECUR>>>();
    logits_kernel<<<dim3(4, 2048), 256>>>();
    softmax_kernel<<<T_ * B_, 256>>>(out, bout);
}

// round 9
// speedup vs baseline: 1.4916x; 1.0116x over previous
#include <cuda_runtime.h>
#include <cuda_bf16.h>
#include <mma.h>
#include <cstdint>

using namespace nvcuda;

#define B_  512
#define T_  256
#define V_  1000
#define E_  256
#define H_  512
#define G_  2048   // 4*H

#define LDW 520    // padded bf16 smem pitch (1040B) — conflict-free
#define LDG_ 132   // padded float pitch for gate buffer

// ---------------- fast activations / helpers ----------------
__device__ __forceinline__ float tanh_fast(float x) {
    float y; asm("tanh.approx.f32 %0, %1;" : "=f"(y) : "f"(x)); return y;
}
__device__ __forceinline__ float sigmoid_fast(float x) {
    return fmaf(0.5f, tanh_fast(0.5f * x), 0.5f);
}
__device__ __forceinline__ void st_release_gpu(int* p, int v) {
    asm volatile("st.release.gpu.global.b32 [%0], %1;" :: "l"(p), "r"(v) : "memory");
}
__device__ __forceinline__ int ld_acquire_gpu(const int* p) {
    int v;
    asm volatile("ld.acquire.gpu.global.b32 %0, [%1];" : "=r"(v) : "l"(p) : "memory");
    return v;
}
__device__ __forceinline__ uint32_t smem_u32(const void* p) {
    uint32_t a;
    asm("{ .reg .u64 t; cvta.to.shared.u64 t, %1; cvt.u32.u64 %0, t; }" : "=r"(a) : "l"(p));
    return a;
}
#define CP_ASYNC16(sa, gp) \
    asm volatile("cp.async.cg.shared.global [%0], [%1], 16;" :: "r"(sa), "l"(gp) : "memory")
#define CP_COMMIT()  asm volatile("cp.async.commit_group;" ::: "memory")
#define CP_WAIT1()   asm volatile("cp.async.wait_group 1;" ::: "memory")
#define CP_WAIT0()   asm volatile("cp.async.wait_group 0;" ::: "memory")

// ---------------- static device scratch ----------------
__device__ __align__(16) __nv_bfloat16 g_H[(T_ + 1)][B_][H_];   // h states (~134MB)
__device__ __align__(16) float          g_tab[V_][G_];          // interleaved [v][4*h+q] (8MB)
__device__ __align__(16) __nv_bfloat16  g_Whh[G_][H_];          // bf16 W_hh1 (2MB)
__device__ __align__(16) __nv_bfloat16  g_Wout[1024][H_];       // bf16 W_out padded (1MB)
__device__ __align__(16) float          g_logits[T_ * B_][1024];// fp32 logits scratch (~537MB)
__device__ __align__(16) short          g_chars[T_][B_];
__device__ int g_flags[128 * 32];        // per-(bt,gt) monotone step flags, 128B apart

// ---------------- init ----------------
__global__ void init_kernel(const float* __restrict__ Whh1, const float* __restrict__ WoutF,
                            const void* __restrict__ gt_raw) {
    int stride = gridDim.x * blockDim.x;
    int tid0 = blockIdx.x * blockDim.x + threadIdx.x;
    if (tid0 < 128) g_flags[tid0 * 32] = 0;
    const int* p = (const int*)gt_raw;
    int z = (p[1] == 0) + (p[3] == 0) + (p[5] == 0) + (p[7] == 0) +
            (p[9] == 0) + (p[11] == 0) + (p[13] == 0) + (p[15] == 0);
    int is64 = (z == 8);
    for (int i = tid0; i < G_ * H_; i += stride) {
        ((__nv_bfloat16*)g_Whh)[i] = __float2bfloat16(Whh1[i]);
        if (i < 1024 * H_) {
            float v = (i < V_ * H_) ? WoutF[i] : 0.f;
            ((__nv_bfloat16*)g_Wout)[i] = __float2bfloat16(v);
        }
        if (i < B_ * H_) ((__nv_bfloat16*)g_H)[i] = __float2bfloat16(0.f);
        if (i < T_ * B_) {
            int t = i / B_, b = i % B_;
            int ch = 0;
            if (t > 0) {
                int idx = b * T_ + (t - 1);
                ch = is64 ? (int)((const long long*)gt_raw)[idx] : ((const int*)gt_raw)[idx];
            }
            ((short*)g_chars)[i] = (short)ch;
        }
    }
}

// ---------------- ih gate table (interleaved [v][4*h+q]) ----------------
__global__ void table_kernel(const float* __restrict__ emb, const float* __restrict__ Wih,
                             const float* __restrict__ bih, const float* __restrict__ bhh) {
    int gtile = blockIdx.x;
    int vtile = blockIdx.y;
    __shared__ float sE[64][65];
    __shared__ float sW[64][65];
    float acc[4][4] = {};
    int tm = threadIdx.x >> 4, tn = threadIdx.x & 15;
    for (int kc = 0; kc < 4; kc++) {
        for (int i = threadIdx.x; i < 64 * 64; i += 256) {
            int r = i >> 6, c = i & 63;
            int v = vtile * 64 + r;
            sE[r][c] = (v < V_) ? emb[v * E_ + kc * 64 + c] : 0.f;
            sW[r][c] = Wih[(gtile * 64 + r) * E_ + kc * 64 + c];
        }
        __syncthreads();
        #pragma unroll 8
        for (int k = 0; k < 64; k++) {
            float e[4], w[4];
            #pragma unroll
            for (int mi = 0; mi < 4; mi++) e[mi] = sE[tm * 4 + mi][k];
            #pragma unroll
            for (int ni = 0; ni < 4; ni++) w[ni] = sW[tn * 4 + ni][k];
            #pragma unroll
            for (int mi = 0; mi < 4; mi++)
                #pragma unroll
                for (int ni = 0; ni < 4; ni++) acc[mi][ni] += e[mi] * w[ni];
        }
        __syncthreads();
    }
    #pragma unroll
    for (int mi = 0; mi < 4; mi++) {
        int v = vtile * 64 + tm * 4 + mi;
        if (v >= V_) continue;
        #pragma unroll
        for (int ni = 0; ni < 4; ni++) {
            int g = gtile * 64 + tn * 4 + ni;            // gate-major index q*512+h
            g_tab[v][(g & 511) * 4 + (g >> 9)] = acc[mi][ni] + bih[g] + bhh[g];
        }
    }
}

// ---------------- persistent recurrence (round-8 + cp.async pipelined staging) ----------------
// 128 blocks: bt = bid>>4 (8 x 64 batch), gt = bid&15 (16 x 32 h-cols -> 128 gate cols).
#define SMEM_RECUR ((128 * LDW + 64 * LDW) * 2)

__global__ __launch_bounds__(256, 1) void recur_kernel() {
    extern __shared__ __nv_bfloat16 smem[];
    __nv_bfloat16* sW = smem;               // 128 x LDW
    __nv_bfloat16* sA = smem + 128 * LDW;   // 64 x LDW
    float* sG = (float*)sA;                 // 64 x LDG_ (reuse after GEMM)

    const int gt = blockIdx.x & 15;
    const int bt = blockIdx.x >> 4;
    const int b0 = bt * 64;
    const int tid = threadIdx.x;

    // stage W slice once: row r: gate q=r>>5, h-col gt*32+(r&31)
    for (int i = tid; i < 128 * 64; i += 256) {
        int r = i >> 6, c = i & 63;
        int grow = (r >> 5) * H_ + gt * 32 + (r & 31);
        ((uint4*)(sW + r * LDW))[c] = *(const uint4*)&g_Whh[grow][c * 8];
    }
    __syncthreads();

    const int warp = tid >> 5, lane = tid & 31;
    const int wm = warp >> 2;   // 0..1 (32 batch rows)
    const int wn = warp & 3;    // 0..3 (32 gate cols)
    const int hcol = gt * 32 + lane;   // pointwise h column for this thread
    const uint32_t sAaddr = smem_u32(sA);

    int* myflag = &g_flags[(bt * 16 + gt) * 32];
    int* peerflag = &g_flags[(bt * 16 + (tid & 15)) * 32];

    float creg[8];
    #pragma unroll
    for (int j = 0; j < 8; j++) creg[j] = 0.f;

    for (int t = 0; t < T_; t++) {
        // prefetch chars (depend only on t; 8 regs)
        short chs[8];
        #pragma unroll
        for (int k = 0; k < 8; k++) chs[k] = g_chars[t][b0 + warp + 8 * k];

        // stage A = h_t [64 x 512] via cp.async, split into two K-halves
        #pragma unroll
        for (int i = tid; i < 2048; i += 256) {              // cols 0..255
            int r = i >> 5, c = i & 31;
            CP_ASYNC16(sAaddr + (uint32_t)((r * LDW + c * 8) * 2),
                       (const char*)&g_H[t][b0 + r][c * 8]);
        }
        CP_COMMIT();
        #pragma unroll
        for (int i = tid; i < 2048; i += 256) {              // cols 256..511
            int r = i >> 5, c = (i & 31) + 32;
            CP_ASYNC16(sAaddr + (uint32_t)((r * LDW + c * 8) * 2),
                       (const char*)&g_H[t][b0 + r][c * 8]);
        }
        CP_COMMIT();

        wmma::fragment<wmma::accumulator, 16, 16, 16, float> acc[2][2];
        #pragma unroll
        for (int mi = 0; mi < 2; mi++)
            #pragma unroll
            for (int ni = 0; ni < 2; ni++) wmma::fill_fragment(acc[mi][ni], 0.f);

        CP_WAIT1();          // first K-half landed
        __syncthreads();

        #pragma unroll 4
        for (int kk = 0; kk < 16; kk++) {
            wmma::fragment<wmma::matrix_b, 16, 16, 16, __nv_bfloat16, wmma::col_major> fb[2];
            #pragma unroll
            for (int ni = 0; ni < 2; ni++)
                wmma::load_matrix_sync(fb[ni], sW + (wn * 32 + ni * 16) * LDW + kk * 16, LDW);
            #pragma unroll
            for (int mi = 0; mi < 2; mi++) {
                wmma::fragment<wmma::matrix_a, 16, 16, 16, __nv_bfloat16, wmma::row_major> fa;
                wmma::load_matrix_sync(fa, sA + (wm * 32 + mi * 16) * LDW + kk * 16, LDW);
                #pragma unroll
                for (int ni = 0; ni < 2; ni++)
                    wmma::mma_sync(acc[mi][ni], fa, fb[ni], acc[mi][ni]);
            }
        }

        CP_WAIT0();          // second K-half landed (hidden under first-half GEMM)
        __syncthreads();

        #pragma unroll 4
        for (int kk = 16; kk < 32; kk++) {
            wmma::fragment<wmma::matrix_b, 16, 16, 16, __nv_bfloat16, wmma::col_major> fb[2];
            #pragma unroll
            for (int ni = 0; ni < 2; ni++)
                wmma::load_matrix_sync(fb[ni], sW + (wn * 32 + ni * 16) * LDW + kk * 16, LDW);
            #pragma unroll
            for (int mi = 0; mi < 2; mi++) {
                wmma::fragment<wmma::matrix_a, 16, 16, 16, __nv_bfloat16, wmma::row_major> fa;
                wmma::load_matrix_sync(fa, sA + (wm * 32 + mi * 16) * LDW + kk * 16, LDW);
                #pragma unroll
                for (int ni = 0; ni < 2; ni++)
                    wmma::mma_sync(acc[mi][ni], fa, fb[ni], acc[mi][ni]);
            }
        }
        __syncthreads();

        #pragma unroll
        for (int mi = 0; mi < 2; mi++)
            #pragma unroll
            for (int ni = 0; ni < 2; ni++)
                wmma::store_matrix_sync(sG + (wm * 32 + mi * 16) * LDG_ + (wn * 32 + ni * 16),
                                        acc[mi][ni], LDG_, wmma::mem_row_major);
        __syncthreads();

        // fused LSTM pointwise; one coalesced float4 tab load per element
        #pragma unroll
        for (int k = 0; k < 8; k++) {
            int bl = warp + 8 * k;
            float4 tb = ((const float4*)g_tab[(int)chs[k]])[hcol];
            float gi = sG[bl * LDG_ + lane]      + tb.x;
            float gf = sG[bl * LDG_ + 32 + lane] + tb.y;
            float gg = sG[bl * LDG_ + 64 + lane] + tb.z;
            float go = sG[bl * LDG_ + 96 + lane] + tb.w;
            gi = sigmoid_fast(gi);
            gf = sigmoid_fast(gf);
            gg = tanh_fast(gg);
            go = sigmoid_fast(go);
            float c = fmaf(gf, creg[k], gi * gg);
            creg[k] = c;
            g_H[t + 1][b0 + bl][hcol] = __float2bfloat16(go * tanh_fast(c));
        }

        // release/acquire barrier across the 16 gt blocks of this bt
        __syncthreads();
        if (tid == 0) st_release_gpu(myflag, t + 1);
        if (tid < 16) {
            while (ld_acquire_gpu(peerflag) < t + 1) __nanosleep(32);
        }
        __syncthreads();
    }
}

// ---------------- batched output projection: block 128m x 256n, warp tile 64x64 ----------------
#define LOGITS_SMEM ((128 * 72 + 256 * 72) * 2)

__global__ __launch_bounds__(256, 1) void logits_kernel() {
    extern __shared__ __nv_bfloat16 lsm[];
    __nv_bfloat16* sA = lsm;             // 128 x 72
    __nv_bfloat16* sB = lsm + 128 * 72;  // 256 x 72
    const __nv_bfloat16* A = &g_H[1][0][0];  // [131072][512]

    int nt = blockIdx.x, mt = blockIdx.y;
    int warp = threadIdx.x >> 5;
    int wm = warp >> 2;   // 0..1 -> 64 rows
    int wn = warp & 3;    // 0..3 -> 64 cols
    wmma::fragment<wmma::accumulator, 16, 16, 16, float> acc[4][4];
    #pragma unroll
    for (int mi = 0; mi < 4; mi++)
        #pragma unroll
        for (int ni = 0; ni < 4; ni++) wmma::fill_fragment(acc[mi][ni], 0.f);

    for (int kc = 0; kc < 8; kc++) {
        #pragma unroll
        for (int i = threadIdx.x; i < 1024; i += 256) {   // A chunk 128x64
            int r = i >> 3, c8 = i & 7;
            *(uint4*)(sA + r * 72 + c8 * 8) =
                *(const uint4*)&A[(mt * 128 + r) * 512 + kc * 64 + c8 * 8];
        }
        #pragma unroll
        for (int i = threadIdx.x; i < 2048; i += 256) {   // B chunk 256x64
            int n = i >> 3, c8 = i & 7;
            *(uint4*)(sB + n * 72 + c8 * 8) =
                *(const uint4*)&g_Wout[nt * 256 + n][kc * 64 + c8 * 8];
        }
        __syncthreads();
        #pragma unroll
        for (int kk = 0; kk < 4; kk++) {
            wmma::fragment<wmma::matrix_a, 16, 16, 16, __nv_bfloat16, wmma::row_major> fa[4];
            #pragma unroll
            for (int mi = 0; mi < 4; mi++)
                wmma::load_matrix_sync(fa[mi], sA + (wm * 64 + mi * 16) * 72 + kk * 16, 72);
            #pragma unroll
            for (int ni = 0; ni < 4; ni++) {
                wmma::fragment<wmma::matrix_b, 16, 16, 16, __nv_bfloat16, wmma::col_major> fb;
                wmma::load_matrix_sync(fb, sB + (wn * 64 + ni * 16) * 72 + kk * 16, 72);
                #pragma unroll
                for (int mi = 0; mi < 4; mi++)
                    wmma::mma_sync(acc[mi][ni], fa[mi], fb, acc[mi][ni]);
            }
        }
        __syncthreads();
    }
    #pragma unroll
    for (int mi = 0; mi < 4; mi++)
        #pragma unroll
        for (int ni = 0; ni < 4; ni++) {
            int row = mt * 128 + wm * 64 + mi * 16;
            int col = nt * 256 + wn * 64 + ni * 16;
            wmma::store_matrix_sync(&g_logits[row][col], acc[mi][ni], 1024, wmma::mem_row_major);
        }
}

// ---------------- log_softmax + bias + remap (round-4, known-good) ----------------
__global__ __launch_bounds__(256, 4) void softmax_kernel(float* __restrict__ out,
                                                         const float* __restrict__ bout) {
    int row = blockIdx.x;
    int t = row >> 9, b = row & 511;
    const float* lg = g_logits[row];
    __shared__ float red[8];

    int lane = threadIdx.x & 31;
    int warp = threadIdx.x >> 5;

    float v[4];
    float mx = -1e30f;
    #pragma unroll
    for (int j = 0; j < 4; j++) {
        int c = threadIdx.x + j * 256;
        v[j] = (c < V_) ? (lg[c] + bout[c]) : -1e30f;
        mx = fmaxf(mx, v[j]);
    }
    #pragma unroll
    for (int s = 16; s > 0; s >>= 1) mx = fmaxf(mx, __shfl_xor_sync(0xFFFFFFFF, mx, s));
    if (lane == 0) red[warp] = mx;
    __syncthreads();
    float m0 = red[lane & 7];
    #pragma unroll
    for (int s = 4; s > 0; s >>= 1) m0 = fmaxf(m0, __shfl_xor_sync(0xFFFFFFFF, m0, s));
    mx = m0;

    float sum = 0.f;
    #pragma unroll
    for (int j = 0; j < 4; j++) {
        int c = threadIdx.x + j * 256;
        if (c < V_) sum += __expf(v[j] - mx);
    }
    #pragma unroll
    for (int s = 16; s > 0; s >>= 1) sum += __shfl_xor_sync(0xFFFFFFFF, sum, s);
    __syncthreads();
    if (lane == 0) red[warp] = sum;
    __syncthreads();
    float s0 = red[lane & 7];
    #pragma unroll
    for (int s = 4; s > 0; s >>= 1) s0 += __shfl_xor_sync(0xFFFFFFFF, s0, s);
    float lse = mx + logf(s0);

    float* o = out + ((size_t)b * T_ + t) * V_;
    #pragma unroll
    for (int j = 0; j < 4; j++) {
        int c = threadIdx.x + j * 256;
        if (c < V_) o[c] = v[j] - lse;
    }
}

// ---------------- launch ----------------
extern "C" void kernel_launch(void* const* d_in, const int* in_sizes, int n_in,
                              void* d_out, int out_size) {
    const void*  gt   = d_in[1];
    const float* emb  = (const float*)d_in[2];
    const float* Wih1 = (const float*)d_in[7];
    const float* Whh1 = (const float*)d_in[8];
    const float* bih1 = (const float*)d_in[9];
    const float* bhh1 = (const float*)d_in[10];
    const float* Wout = (const float*)d_in[11];
    const float* bout = (const float*)d_in[12];
    float* out = (float*)d_out;

    cudaFuncSetAttribute(recur_kernel, cudaFuncAttributeMaxDynamicSharedMemorySize, SMEM_RECUR);
    cudaFuncSetAttribute(logits_kernel, cudaFuncAttributeMaxDynamicSharedMemorySize, LOGITS_SMEM);

    init_kernel<<<1024, 256>>>(Whh1, Wout, gt);
    table_kernel<<<dim3(32, 16), 256>>>(emb, Wih1, bih1, bhh1);
    recur_kernel<<<128, 256, SMEM_RECUR>>>();
    logits_kernel<<<dim3(4, 1024), 256, LOGITS_SMEM>>>();
    softmax_kernel<<<T_ * B_, 256>>>(out, bout);
}

// round 10
// speedup vs baseline: 1.5643x; 1.0487x over previous
#include <cuda_runtime.h>
#include <cuda_bf16.h>
#include <cuda_fp16.h>
#include <mma.h>
#include <cstdint>

using namespace nvcuda;

#define B_  512
#define T_  256
#define V_  1000
#define E_  256
#define H_  512
#define G_  2048   // 4*H

#define LDW 520    // padded bf16 smem pitch (1040B) — conflict-free
#define LDG_ 132   // padded float pitch for gate buffer

// ---------------- fast activations / helpers ----------------
__device__ __forceinline__ float tanh_fast(float x) {
    float y; asm("tanh.approx.f32 %0, %1;" : "=f"(y) : "f"(x)); return y;
}
__device__ __forceinline__ float sigmoid_fast(float x) {
    return fmaf(0.5f, tanh_fast(0.5f * x), 0.5f);
}
__device__ __forceinline__ void st_release_gpu(int* p, int v) {
    asm volatile("st.release.gpu.global.b32 [%0], %1;" :: "l"(p), "r"(v) : "memory");
}
__device__ __forceinline__ int ld_acquire_gpu(const int* p) {
    int v;
    asm volatile("ld.acquire.gpu.global.b32 %0, [%1];" : "=r"(v) : "l"(p) : "memory");
    return v;
}
__device__ __forceinline__ uint32_t smem_u32(const void* p) {
    uint32_t a;
    asm("{ .reg .u64 t; cvta.to.shared.u64 t, %1; cvt.u32.u64 %0, t; }" : "=r"(a) : "l"(p));
    return a;
}
#define CP_ASYNC16(sa, gp) \
    asm volatile("cp.async.cg.shared.global [%0], [%1], 16;" :: "r"(sa), "l"(gp) : "memory")
#define CP_COMMIT()  asm volatile("cp.async.commit_group;" ::: "memory")
#define CP_WAIT1()   asm volatile("cp.async.wait_group 1;" ::: "memory")
#define CP_WAIT0()   asm volatile("cp.async.wait_group 0;" ::: "memory")
#define LDMATRIX_X4(r0, r1, r2, r3, addr) \
    asm volatile("ldmatrix.sync.aligned.m8n8.x4.shared.b16 {%0,%1,%2,%3}, [%4];" \
        : "=r"(r0), "=r"(r1), "=r"(r2), "=r"(r3) : "r"(addr))
#define MMA_16816(d, a0, a1, a2, a3, b0, b1) \
    asm volatile("mma.sync.aligned.m16n8k16.row.col.f32.bf16.bf16.f32 " \
        "{%0,%1,%2,%3}, {%4,%5,%6,%7}, {%8,%9}, {%0,%1,%2,%3};" \
        : "+f"(d[0]), "+f"(d[1]), "+f"(d[2]), "+f"(d[3]) \
        : "r"(a0), "r"(a1), "r"(a2), "r"(a3), "r"(b0), "r"(b1))

// ---------------- static device scratch ----------------
__device__ __align__(16) __nv_bfloat16 g_H[(T_ + 1)][B_][H_];   // h states (~134MB)
__device__ __align__(16) float          g_tab[V_][G_];          // interleaved [v][4*h+q] (8MB)
__device__ __align__(16) __nv_bfloat16  g_Whh[G_][H_];          // bf16 W_hh1 (2MB)
__device__ __align__(16) __nv_bfloat16  g_Wout[1024][H_];       // bf16 W_out padded (1MB)
__device__ __align__(16) __half         g_logits[T_ * B_][1024];// fp16 logits scratch (268MB)
__device__ __align__(16) short          g_chars[T_][B_];
__device__ int g_flags[128 * 32];        // per-(bt,gt) monotone step flags, 128B apart

// ---------------- init ----------------
__global__ void init_kernel(const float* __restrict__ Whh1, const float* __restrict__ WoutF,
                            const void* __restrict__ gt_raw) {
    int stride = gridDim.x * blockDim.x;
    int tid0 = blockIdx.x * blockDim.x + threadIdx.x;
    if (tid0 < 128) g_flags[tid0 * 32] = 0;
    const int* p = (const int*)gt_raw;
    int z = (p[1] == 0) + (p[3] == 0) + (p[5] == 0) + (p[7] == 0) +
            (p[9] == 0) + (p[11] == 0) + (p[13] == 0) + (p[15] == 0);
    int is64 = (z == 8);
    for (int i = tid0; i < G_ * H_; i += stride) {
        ((__nv_bfloat16*)g_Whh)[i] = __float2bfloat16(Whh1[i]);
        if (i < 1024 * H_) {
            float v = (i < V_ * H_) ? WoutF[i] : 0.f;
            ((__nv_bfloat16*)g_Wout)[i] = __float2bfloat16(v);
        }
        if (i < B_ * H_) ((__nv_bfloat16*)g_H)[i] = __float2bfloat16(0.f);
        if (i < T_ * B_) {
            int t = i / B_, b = i % B_;
            int ch = 0;
            if (t > 0) {
                int idx = b * T_ + (t - 1);
                ch = is64 ? (int)((const long long*)gt_raw)[idx] : ((const int*)gt_raw)[idx];
            }
            ((short*)g_chars)[i] = (short)ch;
        }
    }
}

// ---------------- ih gate table (interleaved [v][4*h+q]) ----------------
__global__ void table_kernel(const float* __restrict__ emb, const float* __restrict__ Wih,
                             const float* __restrict__ bih, const float* __restrict__ bhh) {
    int gtile = blockIdx.x;
    int vtile = blockIdx.y;
    __shared__ float sE[64][65];
    __shared__ float sW[64][65];
    float acc[4][4] = {};
    int tm = threadIdx.x >> 4, tn = threadIdx.x & 15;
    for (int kc = 0; kc < 4; kc++) {
        for (int i = threadIdx.x; i < 64 * 64; i += 256) {
            int r = i >> 6, c = i & 63;
            int v = vtile * 64 + r;
            sE[r][c] = (v < V_) ? emb[v * E_ + kc * 64 + c] : 0.f;
            sW[r][c] = Wih[(gtile * 64 + r) * E_ + kc * 64 + c];
        }
        __syncthreads();
        #pragma unroll 8
        for (int k = 0; k < 64; k++) {
            float e[4], w[4];
            #pragma unroll
            for (int mi = 0; mi < 4; mi++) e[mi] = sE[tm * 4 + mi][k];
            #pragma unroll
            for (int ni = 0; ni < 4; ni++) w[ni] = sW[tn * 4 + ni][k];
            #pragma unroll
            for (int mi = 0; mi < 4; mi++)
                #pragma unroll
                for (int ni = 0; ni < 4; ni++) acc[mi][ni] += e[mi] * w[ni];
        }
        __syncthreads();
    }
    #pragma unroll
    for (int mi = 0; mi < 4; mi++) {
        int v = vtile * 64 + tm * 4 + mi;
        if (v >= V_) continue;
        #pragma unroll
        for (int ni = 0; ni < 4; ni++) {
            int g = gtile * 64 + tn * 4 + ni;            // gate-major index q*512+h
            g_tab[v][(g & 511) * 4 + (g >> 9)] = acc[mi][ni] + bih[g] + bhh[g];
        }
    }
}

// ---------------- persistent recurrence (round-9, unchanged) ----------------
#define SMEM_RECUR ((128 * LDW + 64 * LDW) * 2)

__global__ __launch_bounds__(256, 1) void recur_kernel() {
    extern __shared__ __nv_bfloat16 smem[];
    __nv_bfloat16* sW = smem;               // 128 x LDW
    __nv_bfloat16* sA = smem + 128 * LDW;   // 64 x LDW
    float* sG = (float*)sA;                 // 64 x LDG_ (reuse after GEMM)

    const int gt = blockIdx.x & 15;
    const int bt = blockIdx.x >> 4;
    const int b0 = bt * 64;
    const int tid = threadIdx.x;

    for (int i = tid; i < 128 * 64; i += 256) {
        int r = i >> 6, c = i & 63;
        int grow = (r >> 5) * H_ + gt * 32 + (r & 31);
        ((uint4*)(sW + r * LDW))[c] = *(const uint4*)&g_Whh[grow][c * 8];
    }
    __syncthreads();

    const int warp = tid >> 5, lane = tid & 31;
    const int wm = warp >> 2;
    const int wn = warp & 3;
    const int hcol = gt * 32 + lane;
    const uint32_t sAaddr = smem_u32(sA);

    int* myflag = &g_flags[(bt * 16 + gt) * 32];
    int* peerflag = &g_flags[(bt * 16 + (tid & 15)) * 32];

    float creg[8];
    #pragma unroll
    for (int j = 0; j < 8; j++) creg[j] = 0.f;

    for (int t = 0; t < T_; t++) {
        short chs[8];
        #pragma unroll
        for (int k = 0; k < 8; k++) chs[k] = g_chars[t][b0 + warp + 8 * k];

        #pragma unroll
        for (int i = tid; i < 2048; i += 256) {              // cols 0..255
            int r = i >> 5, c = i & 31;
            CP_ASYNC16(sAaddr + (uint32_t)((r * LDW + c * 8) * 2),
                       (const char*)&g_H[t][b0 + r][c * 8]);
        }
        CP_COMMIT();
        #pragma unroll
        for (int i = tid; i < 2048; i += 256) {              // cols 256..511
            int r = i >> 5, c = (i & 31) + 32;
            CP_ASYNC16(sAaddr + (uint32_t)((r * LDW + c * 8) * 2),
                       (const char*)&g_H[t][b0 + r][c * 8]);
        }
        CP_COMMIT();

        wmma::fragment<wmma::accumulator, 16, 16, 16, float> acc[2][2];
        #pragma unroll
        for (int mi = 0; mi < 2; mi++)
            #pragma unroll
            for (int ni = 0; ni < 2; ni++) wmma::fill_fragment(acc[mi][ni], 0.f);

        CP_WAIT1();
        __syncthreads();

        #pragma unroll 4
        for (int kk = 0; kk < 16; kk++) {
            wmma::fragment<wmma::matrix_b, 16, 16, 16, __nv_bfloat16, wmma::col_major> fb[2];
            #pragma unroll
            for (int ni = 0; ni < 2; ni++)
                wmma::load_matrix_sync(fb[ni], sW + (wn * 32 + ni * 16) * LDW + kk * 16, LDW);
            #pragma unroll
            for (int mi = 0; mi < 2; mi++) {
                wmma::fragment<wmma::matrix_a, 16, 16, 16, __nv_bfloat16, wmma::row_major> fa;
                wmma::load_matrix_sync(fa, sA + (wm * 32 + mi * 16) * LDW + kk * 16, LDW);
                #pragma unroll
                for (int ni = 0; ni < 2; ni++)
                    wmma::mma_sync(acc[mi][ni], fa, fb[ni], acc[mi][ni]);
            }
        }

        CP_WAIT0();
        __syncthreads();

        #pragma unroll 4
        for (int kk = 16; kk < 32; kk++) {
            wmma::fragment<wmma::matrix_b, 16, 16, 16, __nv_bfloat16, wmma::col_major> fb[2];
            #pragma unroll
            for (int ni = 0; ni < 2; ni++)
                wmma::load_matrix_sync(fb[ni], sW + (wn * 32 + ni * 16) * LDW + kk * 16, LDW);
            #pragma unroll
            for (int mi = 0; mi < 2; mi++) {
                wmma::fragment<wmma::matrix_a, 16, 16, 16, __nv_bfloat16, wmma::row_major> fa;
                wmma::load_matrix_sync(fa, sA + (wm * 32 + mi * 16) * LDW + kk * 16, LDW);
                #pragma unroll
                for (int ni = 0; ni < 2; ni++)
                    wmma::mma_sync(acc[mi][ni], fa, fb[ni], acc[mi][ni]);
            }
        }
        __syncthreads();

        #pragma unroll
        for (int mi = 0; mi < 2; mi++)
            #pragma unroll
            for (int ni = 0; ni < 2; ni++)
                wmma::store_matrix_sync(sG + (wm * 32 + mi * 16) * LDG_ + (wn * 32 + ni * 16),
                                        acc[mi][ni], LDG_, wmma::mem_row_major);
        __syncthreads();

        #pragma unroll
        for (int k = 0; k < 8; k++) {
            int bl = warp + 8 * k;
            float4 tb = ((const float4*)g_tab[(int)chs[k]])[hcol];
            float gi = sG[bl * LDG_ + lane]      + tb.x;
            float gf = sG[bl * LDG_ + 32 + lane] + tb.y;
            float gg = sG[bl * LDG_ + 64 + lane] + tb.z;
            float go = sG[bl * LDG_ + 96 + lane] + tb.w;
            gi = sigmoid_fast(gi);
            gf = sigmoid_fast(gf);
            gg = tanh_fast(gg);
            go = sigmoid_fast(go);
            float c = fmaf(gf, creg[k], gi * gg);
            creg[k] = c;
            g_H[t + 1][b0 + bl][hcol] = __float2bfloat16(go * tanh_fast(c));
        }

        __syncthreads();
        if (tid == 0) st_release_gpu(myflag, t + 1);
        if (tid < 16) {
            while (ld_acquire_gpu(peerflag) < t + 1) __nanosleep(32);
        }
        __syncthreads();
    }
}

// ---------------- projection: raw mma, block 64m x 256n, direct fp16 stores ----------------
__global__ __launch_bounds__(256, 2) void logits_kernel() {
    __shared__ __nv_bfloat16 sA[64 * 72];    // 9KB
    __shared__ __nv_bfloat16 sB[256 * 72];   // 36KB
    const __nv_bfloat16* A = &g_H[1][0][0];  // [131072][512]

    const int nt = blockIdx.x, mt = blockIdx.y;
    const int tid = threadIdx.x, warp = tid >> 5, lane = tid & 31;
    const int wm = warp >> 2, wn = warp & 3;
    const int g8 = lane >> 2, t4 = lane & 3;

    const uint32_t sA32 = smem_u32(sA), sB32 = smem_u32(sB);
    uint32_t aAddr[2], bAddr[4];
    #pragma unroll
    for (int mi = 0; mi < 2; mi++)
        aAddr[mi] = sA32 + (uint32_t)(((wm * 32 + mi * 16 + (lane & 15)) * 72 + (lane >> 4) * 8) * 2);
    #pragma unroll
    for (int nj = 0; nj < 4; nj++)
        bAddr[nj] = sB32 + (uint32_t)(((wn * 64 + nj * 16 + (lane & 15)) * 72 + (lane >> 4) * 8) * 2);

    float acc[2][8][4];
    #pragma unroll
    for (int mi = 0; mi < 2; mi++)
        #pragma unroll
        for (int n8 = 0; n8 < 8; n8++)
            #pragma unroll
            for (int e = 0; e < 4; e++) acc[mi][n8][e] = 0.f;

    for (int kc = 0; kc < 8; kc++) {
        #pragma unroll
        for (int i = tid; i < 512; i += 256) {               // A chunk 64x64
            int r = i >> 3, c8 = i & 7;
            *(uint4*)(sA + r * 72 + c8 * 8) =
                *(const uint4*)&A[(mt * 64 + r) * 512 + kc * 64 + c8 * 8];
        }
        #pragma unroll
        for (int i = tid; i < 2048; i += 256) {              // B chunk 256x64
            int n = i >> 3, c8 = i & 7;
            *(uint4*)(sB + n * 72 + c8 * 8) =
                *(const uint4*)&g_Wout[nt * 256 + n][kc * 64 + c8 * 8];
        }
        __syncthreads();
        #pragma unroll
        for (int kk = 0; kk < 4; kk++) {
            uint32_t a[2][4];
            #pragma unroll
            for (int mi = 0; mi < 2; mi++)
                LDMATRIX_X4(a[mi][0], a[mi][1], a[mi][2], a[mi][3], aAddr[mi] + kk * 32);
            #pragma unroll
            for (int nj = 0; nj < 4; nj++) {
                uint32_t bm[4];
                LDMATRIX_X4(bm[0], bm[1], bm[2], bm[3], bAddr[nj] + kk * 32);
                #pragma unroll
                for (int mi = 0; mi < 2; mi++) {
                    MMA_16816(acc[mi][nj * 2 + 0], a[mi][0], a[mi][1], a[mi][2], a[mi][3],
                              bm[0], bm[2]);
                    MMA_16816(acc[mi][nj * 2 + 1], a[mi][0], a[mi][1], a[mi][2], a[mi][3],
                              bm[1], bm[3]);
                }
            }
        }
        __syncthreads();
    }

    // direct fp16 stores from accumulators (layout verified in round 7)
    #pragma unroll
    for (int mi = 0; mi < 2; mi++) {
        int row = mt * 64 + wm * 32 + mi * 16 + g8;
        #pragma unroll
        for (int n8 = 0; n8 < 8; n8++) {
            int col = nt * 256 + wn * 64 + n8 * 8 + 2 * t4;
            *(__half2*)&g_logits[row][col] = __floats2half2_rn(acc[mi][n8][0], acc[mi][n8][1]);
            *(__half2*)&g_logits[row + 8][col] = __floats2half2_rn(acc[mi][n8][2], acc[mi][n8][3]);
        }
    }
}

// ---------------- log_softmax + bias + remap (fp16 input) ----------------
__global__ __launch_bounds__(256, 4) void softmax_kernel(float* __restrict__ out,
                                                         const float* __restrict__ bout) {
    int row = blockIdx.x;
    int t = row >> 9, b = row & 511;
    const __half* lg = g_logits[row];
    __shared__ float red[8];

    int lane = threadIdx.x & 31;
    int warp = threadIdx.x >> 5;

    float v[4];
    float mx = -1e30f;
    #pragma unroll
    for (int j = 0; j < 4; j++) {
        int c = threadIdx.x + j * 256;
        v[j] = (c < V_) ? (__half2float(lg[c]) + bout[c]) : -1e30f;
        mx = fmaxf(mx, v[j]);
    }
    #pragma unroll
    for (int s = 16; s > 0; s >>= 1) mx = fmaxf(mx, __shfl_xor_sync(0xFFFFFFFF, mx, s));
    if (lane == 0) red[warp] = mx;
    __syncthreads();
    float m0 = red[lane & 7];
    #pragma unroll
    for (int s = 4; s > 0; s >>= 1) m0 = fmaxf(m0, __shfl_xor_sync(0xFFFFFFFF, m0, s));
    mx = m0;

    float sum = 0.f;
    #pragma unroll
    for (int j = 0; j < 4; j++) {
        int c = threadIdx.x + j * 256;
        if (c < V_) sum += __expf(v[j] - mx);
    }
    #pragma unroll
    for (int s = 16; s > 0; s >>= 1) sum += __shfl_xor_sync(0xFFFFFFFF, sum, s);
    __syncthreads();
    if (lane == 0) red[warp] = sum;
    __syncthreads();
    float s0 = red[lane & 7];
    #pragma unroll
    for (int s = 4; s > 0; s >>= 1) s0 += __shfl_xor_sync(0xFFFFFFFF, s0, s);
    float lse = mx + logf(s0);

    float* o = out + ((size_t)b * T_ + t) * V_;
    #pragma unroll
    for (int j = 0; j < 4; j++) {
        int c = threadIdx.x + j * 256;
        if (c < V_) o[c] = v[j] - lse;
    }
}

// ---------------- launch ----------------
extern "C" void kernel_launch(void* const* d_in, const int* in_sizes, int n_in,
                              void* d_out, int out_size) {
    const void*  gt   = d_in[1];
    const float* emb  = (const float*)d_in[2];
    const float* Wih1 = (const float*)d_in[7];
    const float* Whh1 = (const float*)d_in[8];
    const float* bih1 = (const float*)d_in[9];
    const float* bhh1 = (const float*)d_in[10];
    const float* Wout = (const float*)d_in[11];
    const float* bout = (const float*)d_in[12];
    float* out = (float*)d_out;

    cudaFuncSetAttribute(recur_kernel, cudaFuncAttributeMaxDynamicSharedMemorySize, SMEM_RECUR);

    init_kernel<<<1024, 256>>>(Whh1, Wout, gt);
    table_kernel<<<dim3(32, 16), 256>>>(emb, Wih1, bih1, bhh1);
    recur_kernel<<<128, 256, SMEM_RECUR>>>();
    logits_kernel<<<dim3(4, 2048), 256>>>();
    softmax_kernel<<<T_ * B_, 256>>>(out, bout);
}